// round 2
// baseline (speedup 1.0000x reference)
#include <cuda_runtime.h>
#include <cstdint>
#include <math.h>

#define N_FEAT 120
#define M_COLS 128
#define GS_STRIDE 128          // was 124: BUG — tile is 128 atoms wide, rows overlapped
#define ATOMS_PER_BLOCK 128
#define THREADS 256

// Precomputed linear map: out[z,w] = sum_k G[z,k] * g_M[k*M_COLS + w]
__device__ float g_M[N_FEAT * M_COLS];

// ---------------------------------------------------------------------------
// Prep kernel: fold field_features + all weights into M[120][128] (cols >=120 zero)
// ---------------------------------------------------------------------------
__global__ void build_M_kernel(const float* __restrict__ f,
                               const float* __restrict__ w000,
                               const float* __restrict__ w011,
                               const float* __restrict__ w101,
                               const float* __restrict__ w110,
                               const float* __restrict__ w112,
                               const float* __restrict__ w202,
                               const float* __restrict__ w211,
                               const float* __restrict__ wl0,
                               const float* __restrict__ wl1,
                               const float* __restrict__ wl2) {
    int idx = blockIdx.x * blockDim.x + threadIdx.x;
    if (idx >= N_FEAT * M_COLS) return;
    int k = idx / M_COLS;   // input feature index
    int w = idx % M_COLS;   // output feature index (padded)
    if (w >= N_FEAT) { g_M[idx] = 0.f; return; }

    // Wigner 3j (1,1,2) coefficients, scaled by 1/sqrt(5)
    double Cw[3][3][5];
    #pragma unroll
    for (int a = 0; a < 3; a++)
        #pragma unroll
        for (int b = 0; b < 3; b++)
            #pragma unroll
            for (int c = 0; c < 5; c++) Cw[a][b][c] = 0.0;
    {
        double s2 = 1.0 / sqrt(2.0), s6 = 1.0 / sqrt(6.0);
        Cw[0][2][0] = s2;  Cw[2][0][0] = s2;
        Cw[0][1][1] = s2;  Cw[1][0][1] = s2;
        Cw[1][1][2] = 2.0 * s6; Cw[0][0][2] = -s6; Cw[2][2][2] = -s6;
        Cw[1][2][3] = s2;  Cw[2][1][3] = s2;
        Cw[2][2][4] = s2;  Cw[0][0][4] = -s2;
        double n5 = 1.0 / sqrt(5.0);
        for (int a = 0; a < 3; a++)
            for (int b = 0; b < 3; b++)
                for (int c = 0; c < 5; c++) Cw[a][b][c] *= n5;
    }

    const double INV_S3 = 1.0 / sqrt(3.0);
    const double INV_S5 = 1.0 / sqrt(5.0);
    const double C0v = sqrt(1.0 / 1280.0);  // sqrt(1/(32*32+16*16))
    const double C1v = sqrt(3.0 / 1152.0);  // sqrt(3/(32*16+16*32+8*16))
    const double C2v = sqrt(5.0 / 512.0);   // sqrt(5/(16*16+8*32))

    double val = 0.0;

    if (k < 32) {                       // input is g0[u]
        int u = k;
        if (w < 32) {                   // -> out0[wo]  (w_000 + wl0)
            int wo = w;
            double s = 0.0;
            for (int v = 0; v < 32; v++) s += (double)w000[u*1024 + v*32 + wo] * (double)f[v];
            val = C0v * s + (double)wl0[u*32 + wo] * (1.0 / sqrt(32.0));
        } else if (w < 80) {            // -> out1[wo,j]  (w_011)
            int wo = (w - 32) / 3, j = (w - 32) % 3;
            double s = 0.0;
            for (int v = 0; v < 16; v++) s += (double)w011[u*256 + v*16 + wo] * (double)f[32 + v*3 + j];
            val = C1v * INV_S3 * s;
        }
        // g0 -> out2 : zero
    } else if (k < 80) {                // input is g1[u,i]
        int u = (k - 32) / 3, i = (k - 32) % 3;
        if (w < 32) {                   // -> out0[wo]  (w_110)
            int wo = w;
            double s = 0.0;
            for (int v = 0; v < 16; v++) s += (double)w110[u*512 + v*32 + wo] * (double)f[32 + v*3 + i];
            val = C0v * INV_S3 * s;
        } else if (w < 80) {            // -> out1[wo,j]  (w_101 + wl1, only j==i)
            int wo = (w - 32) / 3, j = (w - 32) % 3;
            if (j == i) {
                double s = 0.0;
                for (int v = 0; v < 32; v++) s += (double)w101[u*512 + v*16 + wo] * (double)f[v];
                val = C1v * INV_S3 * s + (double)wl1[u*16 + wo] * 0.25;
            }
        } else {                        // -> out2[wo,kout]  (w_112 x W3J)
            int wo = (w - 80) / 5, kout = (w - 80) % 5;
            double s = 0.0;
            for (int v = 0; v < 16; v++)
                for (int j2 = 0; j2 < 3; j2++)
                    s += (double)w112[u*128 + v*8 + wo] * Cw[i][j2][kout] * (double)f[32 + v*3 + j2];
            val = C2v * s;
        }
    } else {                            // input is g2[u,i], i in 0..4
        int u = (k - 80) / 5, i = (k - 80) % 5;
        if (w >= 32 && w < 80) {        // -> out1[wo,j]  (w_211 x W3J)
            int wo = (w - 32) / 3, j = (w - 32) % 3;
            double s = 0.0;
            for (int v = 0; v < 16; v++)
                for (int i2 = 0; i2 < 3; i2++)
                    s += (double)w211[u*256 + v*16 + wo] * Cw[i2][j][i] * (double)f[32 + v*3 + i2];
            val = C1v * s;
        } else if (w >= 80) {           // -> out2[wo,j]  (w_202 + wl2, only j==i)
            int wo = (w - 80) / 5, j = (w - 80) % 5;
            if (j == i) {
                double s = 0.0;
                for (int v = 0; v < 32; v++) s += (double)w202[u*256 + v*8 + wo] * (double)f[v];
                val = C2v * INV_S5 * s + (double)wl2[u*8 + wo] * (1.0 / sqrt(8.0));
            }
        }
        // g2 -> out0 : zero
    }

    g_M[idx] = (float)val;
}

// ---------------------------------------------------------------------------
// Main kernel: out[N,120] = G[N,120] @ M  via shared-memory GEMM with f32x2
// Block: 256 threads = 8 output-cols x 32 atom-rows (4 atoms each) = 128 atoms
// Thread (col, row): atoms [row*4, row*4+4), output pairs w = p*16 + col*2
// ---------------------------------------------------------------------------
__global__ __launch_bounds__(THREADS, 1)
void coupling_gemm_kernel(const float* __restrict__ G, float* __restrict__ out, int n) {
    extern __shared__ float smem[];
    float* gs = smem;                             // [120][GS_STRIDE] transposed G tile
    float* Ms = smem + N_FEAT * GS_STRIDE;        // [120][128]

    int tid = threadIdx.x;
    int atom0 = blockIdx.x * ATOMS_PER_BLOCK;

    // Load M into smem (broadcast-friendly; lives in L2 across blocks)
    for (int i = tid; i < N_FEAT * M_COLS; i += THREADS) Ms[i] = g_M[i];

    // Load G tile, transposed: gs[k][atom]. Fully coalesced global reads.
    for (int i = tid; i < ATOMS_PER_BLOCK * N_FEAT; i += THREADS) {
        int a = i / N_FEAT, k = i % N_FEAT;
        int ga = atom0 + a;
        gs[k * GS_STRIDE + a] = (ga < n) ? G[(size_t)ga * N_FEAT + k] : 0.f;
    }
    __syncthreads();

    int col = tid & 7;          // 0..7 : output-pair group
    int a0  = (tid >> 3) * 4;   // first atom of this thread's group

    // 4 atoms x 8 output-pairs, packed f32x2 accumulators
    unsigned long long acc[4][8];
    #pragma unroll
    for (int a = 0; a < 4; a++)
        #pragma unroll
        for (int p = 0; p < 8; p++) acc[a][p] = 0ULL;

    uint32_t ms_base;
    asm("{ .reg .u64 t; cvta.to.shared.u64 t, %1; cvt.u32.u64 %0, t; }"
        : "=r"(ms_base) : "l"(Ms));
    uint32_t maddr0 = ms_base + (uint32_t)(col * 2) * 4u;

    #pragma unroll 8
    for (int k = 0; k < N_FEAT; k++) {
        // 4 atoms' g[k] in one conflict-free LDS.128 (broadcast across 8 cols)
        float4 g = *reinterpret_cast<const float4*>(gs + k * GS_STRIDE + a0);
        unsigned long long gd0, gd1, gd2, gd3;
        asm("mov.b64 %0, {%1, %2};" : "=l"(gd0) : "f"(g.x), "f"(g.x));
        asm("mov.b64 %0, {%1, %2};" : "=l"(gd1) : "f"(g.y), "f"(g.y));
        asm("mov.b64 %0, {%1, %2};" : "=l"(gd2) : "f"(g.z), "f"(g.z));
        asm("mov.b64 %0, {%1, %2};" : "=l"(gd3) : "f"(g.w), "f"(g.w));

        uint32_t maddr = maddr0 + (uint32_t)k * (M_COLS * 4u);
        #pragma unroll
        for (int p = 0; p < 8; p++) {
            // M pair for (k, w=p*16+col*2): 8 cols read 16 consecutive words -> conflict-free
            unsigned long long m;
            asm("ld.shared.b64 %0, [%1];" : "=l"(m) : "r"(maddr + (uint32_t)(p * 64)));
            asm("fma.rn.f32x2 %0, %1, %2, %0;" : "+l"(acc[0][p]) : "l"(gd0), "l"(m));
            asm("fma.rn.f32x2 %0, %1, %2, %0;" : "+l"(acc[1][p]) : "l"(gd1), "l"(m));
            asm("fma.rn.f32x2 %0, %1, %2, %0;" : "+l"(acc[2][p]) : "l"(gd2), "l"(m));
            asm("fma.rn.f32x2 %0, %1, %2, %0;" : "+l"(acc[3][p]) : "l"(gd3), "l"(m));
        }
    }

    // Store: each pair -> out[atom*120 + w], skip padded w >= 120
    #pragma unroll
    for (int a = 0; a < 4; a++) {
        int atom = atom0 + a0 + a;
        if (atom < n) {
            float* orow = out + (size_t)atom * N_FEAT;
            #pragma unroll
            for (int p = 0; p < 8; p++) {
                int w = p * 16 + col * 2;
                if (w < N_FEAT) {
                    float2 v;
                    asm("mov.b64 {%0, %1}, %2;" : "=f"(v.x), "=f"(v.y) : "l"(acc[a][p]));
                    *reinterpret_cast<float2*>(orow + w) = v;
                }
            }
        }
    }
}

// ---------------------------------------------------------------------------
extern "C" void kernel_launch(void* const* d_in, const int* in_sizes, int n_in,
                              void* d_out, int out_size) {
    const float* G    = (const float*)d_in[0];
    const float* f    = (const float*)d_in[1];
    const float* w000 = (const float*)d_in[2];
    const float* w011 = (const float*)d_in[3];
    const float* w101 = (const float*)d_in[4];
    const float* w110 = (const float*)d_in[5];
    const float* w112 = (const float*)d_in[6];
    const float* w202 = (const float*)d_in[7];
    const float* w211 = (const float*)d_in[8];
    const float* wl0  = (const float*)d_in[9];
    const float* wl1  = (const float*)d_in[10];
    const float* wl2  = (const float*)d_in[11];
    float* out = (float*)d_out;

    int n = in_sizes[0] / N_FEAT;

    build_M_kernel<<<(N_FEAT * M_COLS + 127) / 128, 128>>>(
        f, w000, w011, w101, w110, w112, w202, w211, wl0, wl1, wl2);

    int smem_bytes = (N_FEAT * GS_STRIDE + N_FEAT * M_COLS) * (int)sizeof(float);
    cudaFuncSetAttribute(coupling_gemm_kernel,
                         cudaFuncAttributeMaxDynamicSharedMemorySize, smem_bytes);
    int blocks = (n + ATOMS_PER_BLOCK - 1) / ATOMS_PER_BLOCK;
    coupling_gemm_kernel<<<blocks, THREADS, smem_bytes>>>(G, out, n);
}

// round 3
// speedup vs baseline: 1.2818x; 1.2818x over previous
#include <cuda_runtime.h>
#include <cstdint>
#include <math.h>

#define N_FEAT 120
#define M_COLS 128
#define GS_STRIDE 256
#define ATOMS_PER_BLOCK 256
#define THREADS 512

// Precomputed linear map: out[z,w] = sum_k G[z,k] * g_M[k*M_COLS + w]
__device__ float g_M[N_FEAT * M_COLS];

// ---------------------------------------------------------------------------
// Prep kernel: fold field_features + all weights into M[120][128] (cols >=120 zero)
// ---------------------------------------------------------------------------
__global__ void build_M_kernel(const float* __restrict__ f,
                               const float* __restrict__ w000,
                               const float* __restrict__ w011,
                               const float* __restrict__ w101,
                               const float* __restrict__ w110,
                               const float* __restrict__ w112,
                               const float* __restrict__ w202,
                               const float* __restrict__ w211,
                               const float* __restrict__ wl0,
                               const float* __restrict__ wl1,
                               const float* __restrict__ wl2) {
    int idx = blockIdx.x * blockDim.x + threadIdx.x;
    if (idx >= N_FEAT * M_COLS) return;
    int k = idx / M_COLS;   // input feature index
    int w = idx % M_COLS;   // output feature index (padded)
    if (w >= N_FEAT) { g_M[idx] = 0.f; return; }

    // Wigner 3j (1,1,2) coefficients, scaled by 1/sqrt(5)
    double Cw[3][3][5];
    #pragma unroll
    for (int a = 0; a < 3; a++)
        #pragma unroll
        for (int b = 0; b < 3; b++)
            #pragma unroll
            for (int c = 0; c < 5; c++) Cw[a][b][c] = 0.0;
    {
        double s2 = 1.0 / sqrt(2.0), s6 = 1.0 / sqrt(6.0);
        Cw[0][2][0] = s2;  Cw[2][0][0] = s2;
        Cw[0][1][1] = s2;  Cw[1][0][1] = s2;
        Cw[1][1][2] = 2.0 * s6; Cw[0][0][2] = -s6; Cw[2][2][2] = -s6;
        Cw[1][2][3] = s2;  Cw[2][1][3] = s2;
        Cw[2][2][4] = s2;  Cw[0][0][4] = -s2;
        double n5 = 1.0 / sqrt(5.0);
        for (int a = 0; a < 3; a++)
            for (int b = 0; b < 3; b++)
                for (int c = 0; c < 5; c++) Cw[a][b][c] *= n5;
    }

    const double INV_S3 = 1.0 / sqrt(3.0);
    const double INV_S5 = 1.0 / sqrt(5.0);
    const double C0v = sqrt(1.0 / 1280.0);  // sqrt(1/(32*32+16*16))
    const double C1v = sqrt(3.0 / 1152.0);  // sqrt(3/(32*16+16*32+8*16))
    const double C2v = sqrt(5.0 / 512.0);   // sqrt(5/(16*16+8*32))

    double val = 0.0;

    if (k < 32) {                       // input is g0[u]
        int u = k;
        if (w < 32) {                   // -> out0[wo]  (w_000 + wl0)
            int wo = w;
            double s = 0.0;
            for (int v = 0; v < 32; v++) s += (double)w000[u*1024 + v*32 + wo] * (double)f[v];
            val = C0v * s + (double)wl0[u*32 + wo] * (1.0 / sqrt(32.0));
        } else if (w < 80) {            // -> out1[wo,j]  (w_011)
            int wo = (w - 32) / 3, j = (w - 32) % 3;
            double s = 0.0;
            for (int v = 0; v < 16; v++) s += (double)w011[u*256 + v*16 + wo] * (double)f[32 + v*3 + j];
            val = C1v * INV_S3 * s;
        }
        // g0 -> out2 : zero
    } else if (k < 80) {                // input is g1[u,i]
        int u = (k - 32) / 3, i = (k - 32) % 3;
        if (w < 32) {                   // -> out0[wo]  (w_110)
            int wo = w;
            double s = 0.0;
            for (int v = 0; v < 16; v++) s += (double)w110[u*512 + v*32 + wo] * (double)f[32 + v*3 + i];
            val = C0v * INV_S3 * s;
        } else if (w < 80) {            // -> out1[wo,j]  (w_101 + wl1, only j==i)
            int wo = (w - 32) / 3, j = (w - 32) % 3;
            if (j == i) {
                double s = 0.0;
                for (int v = 0; v < 32; v++) s += (double)w101[u*512 + v*16 + wo] * (double)f[v];
                val = C1v * INV_S3 * s + (double)wl1[u*16 + wo] * 0.25;
            }
        } else {                        // -> out2[wo,kout]  (w_112 x W3J)
            int wo = (w - 80) / 5, kout = (w - 80) % 5;
            double s = 0.0;
            for (int v = 0; v < 16; v++)
                for (int j2 = 0; j2 < 3; j2++)
                    s += (double)w112[u*128 + v*8 + wo] * Cw[i][j2][kout] * (double)f[32 + v*3 + j2];
            val = C2v * s;
        }
    } else {                            // input is g2[u,i], i in 0..4
        int u = (k - 80) / 5, i = (k - 80) % 5;
        if (w >= 32 && w < 80) {        // -> out1[wo,j]  (w_211 x W3J)
            int wo = (w - 32) / 3, j = (w - 32) % 3;
            double s = 0.0;
            for (int v = 0; v < 16; v++)
                for (int i2 = 0; i2 < 3; i2++)
                    s += (double)w211[u*256 + v*16 + wo] * Cw[i2][j][i] * (double)f[32 + v*3 + i2];
            val = C1v * s;
        } else if (w >= 80) {           // -> out2[wo,j]  (w_202 + wl2, only j==i)
            int wo = (w - 80) / 5, j = (w - 80) % 5;
            if (j == i) {
                double s = 0.0;
                for (int v = 0; v < 32; v++) s += (double)w202[u*256 + v*8 + wo] * (double)f[v];
                val = C2v * INV_S5 * s + (double)wl2[u*8 + wo] * (1.0 / sqrt(8.0));
            }
        }
        // g2 -> out0 : zero
    }

    g_M[idx] = (float)val;
}

// ---------------------------------------------------------------------------
// Main kernel: out[N,120] = G[N,120] @ M  via shared-memory GEMM with f32x2
// Block: 512 threads = 8 output-cols x 64 atom-rows (4 atoms each) = 256 atoms
// Thread (col, row): atoms [row*4, row*4+4), output pairs w = p*16 + col*2
// ---------------------------------------------------------------------------
__global__ __launch_bounds__(THREADS, 1)
void coupling_gemm_kernel(const float* __restrict__ G, float* __restrict__ out, int n) {
    extern __shared__ float smem[];
    float* gs = smem;                             // [120][GS_STRIDE] transposed G tile
    float* Ms = smem + N_FEAT * GS_STRIDE;        // [120][128]

    int tid = threadIdx.x;
    int atom0 = blockIdx.x * ATOMS_PER_BLOCK;

    // Load M into smem (broadcast-friendly; lives in L2 across blocks)
    for (int i = tid; i < N_FEAT * M_COLS; i += THREADS) Ms[i] = g_M[i];

    // Load G tile, transposed: gs[k][atom]. Fully coalesced global reads.
    for (int i = tid; i < ATOMS_PER_BLOCK * N_FEAT; i += THREADS) {
        int a = i / N_FEAT, k = i % N_FEAT;
        int ga = atom0 + a;
        gs[k * GS_STRIDE + a] = (ga < n) ? G[(size_t)ga * N_FEAT + k] : 0.f;
    }
    __syncthreads();

    int col = tid & 7;          // 0..7 : output-pair group
    int a0  = (tid >> 3) * 4;   // first atom of this thread's group

    // 4 atoms x 8 output-pairs, packed f32x2 accumulators
    unsigned long long acc[4][8];
    #pragma unroll
    for (int a = 0; a < 4; a++)
        #pragma unroll
        for (int p = 0; p < 8; p++) acc[a][p] = 0ULL;

    uint32_t ms_base;
    asm("{ .reg .u64 t; cvta.to.shared.u64 t, %1; cvt.u32.u64 %0, t; }"
        : "=r"(ms_base) : "l"(Ms));
    uint32_t maddr0 = ms_base + (uint32_t)(col * 2) * 4u;

    #pragma unroll 8
    for (int k = 0; k < N_FEAT; k++) {
        // 4 atoms' g[k] in one conflict-free LDS.128 (broadcast across 8 cols)
        float4 g = *reinterpret_cast<const float4*>(gs + k * GS_STRIDE + a0);
        unsigned long long gd0, gd1, gd2, gd3;
        asm("mov.b64 %0, {%1, %2};" : "=l"(gd0) : "f"(g.x), "f"(g.x));
        asm("mov.b64 %0, {%1, %2};" : "=l"(gd1) : "f"(g.y), "f"(g.y));
        asm("mov.b64 %0, {%1, %2};" : "=l"(gd2) : "f"(g.z), "f"(g.z));
        asm("mov.b64 %0, {%1, %2};" : "=l"(gd3) : "f"(g.w), "f"(g.w));

        uint32_t maddr = maddr0 + (uint32_t)k * (M_COLS * 4u);
        #pragma unroll
        for (int p = 0; p < 8; p++) {
            // M pair for (k, w=p*16+col*2): 8 cols read 16 consecutive words -> conflict-free
            unsigned long long m;
            asm("ld.shared.b64 %0, [%1];" : "=l"(m) : "r"(maddr + (uint32_t)(p * 64)));
            asm("fma.rn.f32x2 %0, %1, %2, %0;" : "+l"(acc[0][p]) : "l"(gd0), "l"(m));
            asm("fma.rn.f32x2 %0, %1, %2, %0;" : "+l"(acc[1][p]) : "l"(gd1), "l"(m));
            asm("fma.rn.f32x2 %0, %1, %2, %0;" : "+l"(acc[2][p]) : "l"(gd2), "l"(m));
            asm("fma.rn.f32x2 %0, %1, %2, %0;" : "+l"(acc[3][p]) : "l"(gd3), "l"(m));
        }
    }

    // Store: each pair -> out[atom*120 + w], skip padded w >= 120
    #pragma unroll
    for (int a = 0; a < 4; a++) {
        int atom = atom0 + a0 + a;
        if (atom < n) {
            float* orow = out + (size_t)atom * N_FEAT;
            #pragma unroll
            for (int p = 0; p < 8; p++) {
                int w = p * 16 + col * 2;
                if (w < N_FEAT) {
                    float2 v;
                    asm("mov.b64 {%0, %1}, %2;" : "=f"(v.x), "=f"(v.y) : "l"(acc[a][p]));
                    *reinterpret_cast<float2*>(orow + w) = v;
                }
            }
        }
    }
}

// ---------------------------------------------------------------------------
extern "C" void kernel_launch(void* const* d_in, const int* in_sizes, int n_in,
                              void* d_out, int out_size) {
    const float* G    = (const float*)d_in[0];
    const float* f    = (const float*)d_in[1];
    const float* w000 = (const float*)d_in[2];
    const float* w011 = (const float*)d_in[3];
    const float* w101 = (const float*)d_in[4];
    const float* w110 = (const float*)d_in[5];
    const float* w112 = (const float*)d_in[6];
    const float* w202 = (const float*)d_in[7];
    const float* w211 = (const float*)d_in[8];
    const float* wl0  = (const float*)d_in[9];
    const float* wl1  = (const float*)d_in[10];
    const float* wl2  = (const float*)d_in[11];
    float* out = (float*)d_out;

    int n = in_sizes[0] / N_FEAT;

    build_M_kernel<<<(N_FEAT * M_COLS + 127) / 128, 128>>>(
        f, w000, w011, w101, w110, w112, w202, w211, wl0, wl1, wl2);

    int smem_bytes = (N_FEAT * GS_STRIDE + N_FEAT * M_COLS) * (int)sizeof(float);
    cudaFuncSetAttribute(coupling_gemm_kernel,
                         cudaFuncAttributeMaxDynamicSharedMemorySize, smem_bytes);
    int blocks = (n + ATOMS_PER_BLOCK - 1) / ATOMS_PER_BLOCK;
    coupling_gemm_kernel<<<blocks, THREADS, smem_bytes>>>(G, out, n);
}

// round 4
// speedup vs baseline: 1.5353x; 1.1978x over previous
#include <cuda_runtime.h>
#include <cstdint>
#include <math.h>

#define N_FEAT 120
#define M_COLS 128
#define GS_STRIDE 256
#define ATOMS_PER_BLOCK 256
#define THREADS 512

// Precomputed linear map: out[z,w] = sum_k G[z,k] * g_M[k*M_COLS + w]
__device__ float g_M[N_FEAT * M_COLS];

// ---------------------------------------------------------------------------
// Prep kernel: fold field_features + all weights into M[120][128] (cols >=120 zero)
// ---------------------------------------------------------------------------
__global__ void build_M_kernel(const float* __restrict__ f,
                               const float* __restrict__ w000,
                               const float* __restrict__ w011,
                               const float* __restrict__ w101,
                               const float* __restrict__ w110,
                               const float* __restrict__ w112,
                               const float* __restrict__ w202,
                               const float* __restrict__ w211,
                               const float* __restrict__ wl0,
                               const float* __restrict__ wl1,
                               const float* __restrict__ wl2) {
    int idx = blockIdx.x * blockDim.x + threadIdx.x;
    if (idx >= N_FEAT * M_COLS) return;
    int k = idx / M_COLS;   // input feature index
    int w = idx % M_COLS;   // output feature index (padded)
    if (w >= N_FEAT) { g_M[idx] = 0.f; return; }

    // Wigner 3j (1,1,2) coefficients, scaled by 1/sqrt(5)
    double Cw[3][3][5];
    #pragma unroll
    for (int a = 0; a < 3; a++)
        #pragma unroll
        for (int b = 0; b < 3; b++)
            #pragma unroll
            for (int c = 0; c < 5; c++) Cw[a][b][c] = 0.0;
    {
        double s2 = 1.0 / sqrt(2.0), s6 = 1.0 / sqrt(6.0);
        Cw[0][2][0] = s2;  Cw[2][0][0] = s2;
        Cw[0][1][1] = s2;  Cw[1][0][1] = s2;
        Cw[1][1][2] = 2.0 * s6; Cw[0][0][2] = -s6; Cw[2][2][2] = -s6;
        Cw[1][2][3] = s2;  Cw[2][1][3] = s2;
        Cw[2][2][4] = s2;  Cw[0][0][4] = -s2;
        double n5 = 1.0 / sqrt(5.0);
        for (int a = 0; a < 3; a++)
            for (int b = 0; b < 3; b++)
                for (int c = 0; c < 5; c++) Cw[a][b][c] *= n5;
    }

    const double INV_S3 = 1.0 / sqrt(3.0);
    const double INV_S5 = 1.0 / sqrt(5.0);
    const double C0v = sqrt(1.0 / 1280.0);  // sqrt(1/(32*32+16*16))
    const double C1v = sqrt(3.0 / 1152.0);  // sqrt(3/(32*16+16*32+8*16))
    const double C2v = sqrt(5.0 / 512.0);   // sqrt(5/(16*16+8*32))

    double val = 0.0;

    if (k < 32) {                       // input is g0[u]
        int u = k;
        if (w < 32) {                   // -> out0[wo]  (w_000 + wl0)
            int wo = w;
            double s = 0.0;
            for (int v = 0; v < 32; v++) s += (double)w000[u*1024 + v*32 + wo] * (double)f[v];
            val = C0v * s + (double)wl0[u*32 + wo] * (1.0 / sqrt(32.0));
        } else if (w < 80) {            // -> out1[wo,j]  (w_011)
            int wo = (w - 32) / 3, j = (w - 32) % 3;
            double s = 0.0;
            for (int v = 0; v < 16; v++) s += (double)w011[u*256 + v*16 + wo] * (double)f[32 + v*3 + j];
            val = C1v * INV_S3 * s;
        }
        // g0 -> out2 : zero
    } else if (k < 80) {                // input is g1[u,i]
        int u = (k - 32) / 3, i = (k - 32) % 3;
        if (w < 32) {                   // -> out0[wo]  (w_110)
            int wo = w;
            double s = 0.0;
            for (int v = 0; v < 16; v++) s += (double)w110[u*512 + v*32 + wo] * (double)f[32 + v*3 + i];
            val = C0v * INV_S3 * s;
        } else if (w < 80) {            // -> out1[wo,j]  (w_101 + wl1, only j==i)
            int wo = (w - 32) / 3, j = (w - 32) % 3;
            if (j == i) {
                double s = 0.0;
                for (int v = 0; v < 32; v++) s += (double)w101[u*512 + v*16 + wo] * (double)f[v];
                val = C1v * INV_S3 * s + (double)wl1[u*16 + wo] * 0.25;
            }
        } else {                        // -> out2[wo,kout]  (w_112 x W3J)
            int wo = (w - 80) / 5, kout = (w - 80) % 5;
            double s = 0.0;
            for (int v = 0; v < 16; v++)
                for (int j2 = 0; j2 < 3; j2++)
                    s += (double)w112[u*128 + v*8 + wo] * Cw[i][j2][kout] * (double)f[32 + v*3 + j2];
            val = C2v * s;
        }
    } else {                            // input is g2[u,i], i in 0..4
        int u = (k - 80) / 5, i = (k - 80) % 5;
        if (w >= 32 && w < 80) {        // -> out1[wo,j]  (w_211 x W3J)
            int wo = (w - 32) / 3, j = (w - 32) % 3;
            double s = 0.0;
            for (int v = 0; v < 16; v++)
                for (int i2 = 0; i2 < 3; i2++)
                    s += (double)w211[u*256 + v*16 + wo] * Cw[i2][j][i] * (double)f[32 + v*3 + i2];
            val = C1v * s;
        } else if (w >= 80) {           // -> out2[wo,j]  (w_202 + wl2, only j==i)
            int wo = (w - 80) / 5, j = (w - 80) % 5;
            if (j == i) {
                double s = 0.0;
                for (int v = 0; v < 32; v++) s += (double)w202[u*256 + v*8 + wo] * (double)f[v];
                val = C2v * INV_S5 * s + (double)wl2[u*8 + wo] * (1.0 / sqrt(8.0));
            }
        }
        // g2 -> out0 : zero
    }

    g_M[idx] = (float)val;
}

// ---------------------------------------------------------------------------
// Main kernel: out[N,120] = G[N,120] @ M  via shared-memory GEMM with f32x2.
// G tile stored transposed with XOR swizzle: word(k, a) = k*256 + (a ^ ((kq&7)<<2)),
// kq = k/4. XOR only touches bits >=2 of a, so 4-atom float4 groups stay intact
// (LDS.128 reads work), while transpose stores spread across 8 bank groups
// (32-way -> 4-way STS conflict).
// Block: 512 threads = 8 output-cols x 64 atom-rows (4 atoms each) = 256 atoms.
// ---------------------------------------------------------------------------
__global__ __launch_bounds__(THREADS, 1)
void coupling_gemm_kernel(const float* __restrict__ G, float* __restrict__ out, int n) {
    extern __shared__ float smem[];
    float* gs = smem;                             // [120][GS_STRIDE] swizzled transposed G tile
    float* Ms = smem + N_FEAT * GS_STRIDE;        // [120][128]

    int tid = threadIdx.x;
    int atom0 = blockIdx.x * ATOMS_PER_BLOCK;

    // Load M into smem (coalesced, conflict-free)
    for (int i = tid; i < N_FEAT * M_COLS; i += THREADS) Ms[i] = g_M[i];

    // Load G tile with LDG.128, scatter-transpose with swizzle.
    // i indexes float4 chunks: a = atom-in-block, kq = float4 index along feature dim.
    {
        const float4* G4 = reinterpret_cast<const float4*>(G);
        for (int i = tid; i < ATOMS_PER_BLOCK * (N_FEAT / 4); i += THREADS) {
            int a = i / (N_FEAT / 4), kq = i % (N_FEAT / 4);
            int ga = atom0 + a;
            float4 v = make_float4(0.f, 0.f, 0.f, 0.f);
            if (ga < n) v = G4[(size_t)ga * (N_FEAT / 4) + kq];
            int as = a ^ ((kq & 7) << 2);          // swizzled atom column
            int k0 = kq * 4;
            gs[(k0 + 0) * GS_STRIDE + as] = v.x;
            gs[(k0 + 1) * GS_STRIDE + as] = v.y;
            gs[(k0 + 2) * GS_STRIDE + as] = v.z;
            gs[(k0 + 3) * GS_STRIDE + as] = v.w;
        }
    }
    __syncthreads();

    int col = tid & 7;          // 0..7 : output-pair group
    int a0  = (tid >> 3) * 4;   // first atom of this thread's group

    // 4 atoms x 8 output-pairs, packed f32x2 accumulators
    unsigned long long acc[4][8];
    #pragma unroll
    for (int a = 0; a < 4; a++)
        #pragma unroll
        for (int p = 0; p < 8; p++) acc[a][p] = 0ULL;

    uint32_t ms_base;
    asm("{ .reg .u64 t; cvta.to.shared.u64 t, %1; cvt.u32.u64 %0, t; }"
        : "=r"(ms_base) : "l"(Ms));
    uint32_t maddr0 = ms_base + (uint32_t)(col * 2) * 4u;

    #pragma unroll 2
    for (int kq = 0; kq < N_FEAT / 4; kq++) {
        int a_sw = a0 ^ ((kq & 7) << 2);           // same swizzle for the 4 k in this group
        #pragma unroll
        for (int j = 0; j < 4; j++) {
            int k = kq * 4 + j;
            // 4 atoms' g[k] in one LDS.128 (8-way broadcast, 4 distinct banks)
            float4 g = *reinterpret_cast<const float4*>(gs + k * GS_STRIDE + a_sw);
            unsigned long long gd0, gd1, gd2, gd3;
            asm("mov.b64 %0, {%1, %2};" : "=l"(gd0) : "f"(g.x), "f"(g.x));
            asm("mov.b64 %0, {%1, %2};" : "=l"(gd1) : "f"(g.y), "f"(g.y));
            asm("mov.b64 %0, {%1, %2};" : "=l"(gd2) : "f"(g.z), "f"(g.z));
            asm("mov.b64 %0, {%1, %2};" : "=l"(gd3) : "f"(g.w), "f"(g.w));

            uint32_t maddr = maddr0 + (uint32_t)k * (M_COLS * 4u);
            #pragma unroll
            for (int p = 0; p < 8; p++) {
                // M pair for (k, w=p*16+col*2): 8 cols read 16 consecutive words -> conflict-free
                unsigned long long m;
                asm("ld.shared.b64 %0, [%1];" : "=l"(m) : "r"(maddr + (uint32_t)(p * 64)));
                asm("fma.rn.f32x2 %0, %1, %2, %0;" : "+l"(acc[0][p]) : "l"(gd0), "l"(m));
                asm("fma.rn.f32x2 %0, %1, %2, %0;" : "+l"(acc[1][p]) : "l"(gd1), "l"(m));
                asm("fma.rn.f32x2 %0, %1, %2, %0;" : "+l"(acc[2][p]) : "l"(gd2), "l"(m));
                asm("fma.rn.f32x2 %0, %1, %2, %0;" : "+l"(acc[3][p]) : "l"(gd3), "l"(m));
            }
        }
    }

    // Store: each pair -> out[atom*120 + w], skip padded w >= 120
    #pragma unroll
    for (int a = 0; a < 4; a++) {
        int atom = atom0 + a0 + a;
        if (atom < n) {
            float* orow = out + (size_t)atom * N_FEAT;
            #pragma unroll
            for (int p = 0; p < 8; p++) {
                int w = p * 16 + col * 2;
                if (w < N_FEAT) {
                    float2 v;
                    asm("mov.b64 {%0, %1}, %2;" : "=f"(v.x), "=f"(v.y) : "l"(acc[a][p]));
                    *reinterpret_cast<float2*>(orow + w) = v;
                }
            }
        }
    }
}

// ---------------------------------------------------------------------------
extern "C" void kernel_launch(void* const* d_in, const int* in_sizes, int n_in,
                              void* d_out, int out_size) {
    const float* G    = (const float*)d_in[0];
    const float* f    = (const float*)d_in[1];
    const float* w000 = (const float*)d_in[2];
    const float* w011 = (const float*)d_in[3];
    const float* w101 = (const float*)d_in[4];
    const float* w110 = (const float*)d_in[5];
    const float* w112 = (const float*)d_in[6];
    const float* w202 = (const float*)d_in[7];
    const float* w211 = (const float*)d_in[8];
    const float* wl0  = (const float*)d_in[9];
    const float* wl1  = (const float*)d_in[10];
    const float* wl2  = (const float*)d_in[11];
    float* out = (float*)d_out;

    int n = in_sizes[0] / N_FEAT;

    build_M_kernel<<<(N_FEAT * M_COLS + 127) / 128, 128>>>(
        f, w000, w011, w101, w110, w112, w202, w211, wl0, wl1, wl2);

    int smem_bytes = (N_FEAT * GS_STRIDE + N_FEAT * M_COLS) * (int)sizeof(float);
    cudaFuncSetAttribute(coupling_gemm_kernel,
                         cudaFuncAttributeMaxDynamicSharedMemorySize, smem_bytes);
    int blocks = (n + ATOMS_PER_BLOCK - 1) / ATOMS_PER_BLOCK;
    coupling_gemm_kernel<<<blocks, THREADS, smem_bytes>>>(G, out, n);
}